// round 4
// baseline (speedup 1.0000x reference)
#include <cuda_runtime.h>

// Problem constants
#define BATCH 16
#define SEQ   720
#define CIN   321
#define NORD  64
#define PRED  720
#define M_TOT (BATCH*CIN)        // 5136
#define MPAD  5184               // 81*64
#define TSPLIT 9
#define TCHUNK 80                // 720/9
#define ROW_STRIDE (SEQ*CIN)     // 231120

// ---------------- device scratch (static: no allocation allowed) ----------------
__device__ float g_P2 [NORD*NORD];
__device__ float g_P4 [NORD*NORD];
__device__ float g_P8 [NORD*NORD];
__device__ float g_M16[NORD*NORD];
__device__ float g_seeds[16*NORD];
__device__ float g_Kt [PRED*NORD];      // Kt[t][n] = (A^(719-t) B)[n]
__device__ float g_Spart[16*NORD];
__device__ float g_EW [PRED*NORD];      // (E @ W)[p][m]
__device__ float g_eb [PRED];           // E @ b_mlp
__device__ float g_g  [PRED];           // EW @ S
__device__ float g_XK [TSPLIT][MPAD*NORD];
__device__ float g_XKr[MPAD*NORD];
__device__ float g_rsum[TSPLIT][MPAD];
__device__ float g_rsq [TSPLIT][MPAD];
__device__ float g_mean[MPAD];
__device__ float g_invstd[MPAD];
__device__ float g_std[MPAD];

// ---------------- A^16 by repeated squaring: dst = src*src ----------------
__global__ void pow2_kernel(const float* __restrict__ Ain, int stage) {
    const float* src;
    float* dst;
    if (stage == 0)      { src = Ain;  dst = g_P2;  }
    else if (stage == 1) { src = g_P2; dst = g_P4;  }
    else if (stage == 2) { src = g_P4; dst = g_P8;  }
    else                 { src = g_P8; dst = g_M16; }

    __shared__ float row[NORD];
    int i = blockIdx.x, j = threadIdx.x;
    row[j] = src[i*NORD + j];
    __syncthreads();
    float a0=0.f, a1=0.f, a2=0.f, a3=0.f;
#pragma unroll
    for (int k = 0; k < NORD; k += 4) {
        a0 += row[k+0] * src[(k+0)*NORD + j];
        a1 += row[k+1] * src[(k+1)*NORD + j];
        a2 += row[k+2] * src[(k+2)*NORD + j];
        a3 += row[k+3] * src[(k+3)*NORD + j];
    }
    dst[i*NORD + j] = (a0+a1) + (a2+a3);
}

// ---------------- seeds: u_r = A^r B, r = 0..15 ----------------
__global__ void seeds_kernel(const float* __restrict__ A, const float* __restrict__ Bv) {
    __shared__ float v[NORD];
    int n = threadIdx.x;
    float val = Bv[n];
    v[n] = val;
    g_seeds[n] = val;
    __syncthreads();
    for (int r = 1; r < 16; r++) {
        float a0=0.f, a1=0.f, a2=0.f, a3=0.f;
#pragma unroll
        for (int k = 0; k < NORD; k += 4) {
            a0 += A[n*NORD + k+0] * v[k+0];
            a1 += A[n*NORD + k+1] * v[k+1];
            a2 += A[n*NORD + k+2] * v[k+2];
            a3 += A[n*NORD + k+3] * v[k+3];
        }
        float acc = (a0+a1) + (a2+a3);
        __syncthreads();
        v[n] = acc;
        g_seeds[r*NORD + n] = acc;
        __syncthreads();
    }
}

// ---------------- chains: 16 parallel chains with M = A^16 ----------------
__global__ void chains_kernel() {
    __shared__ float v[NORD];
    int r = blockIdx.x, n = threadIdx.x;
    float mrow[NORD];
#pragma unroll
    for (int k = 0; k < NORD; k++) mrow[k] = g_M16[n*NORD + k];
    v[n] = g_seeds[r*NORD + n];
    float sacc = 0.f;
    __syncthreads();
    for (int j = 0; j < 45; j++) {
        float vn = v[n];
        int t = 719 - (16*j + r);           // exponent s = 16j + r
        g_Kt[t*NORD + n] = vn;
        sacc += vn;
        float a0=0.f, a1=0.f, a2=0.f, a3=0.f;
#pragma unroll
        for (int k = 0; k < NORD; k += 4) {
            a0 += mrow[k+0] * v[k+0];
            a1 += mrow[k+1] * v[k+1];
            a2 += mrow[k+2] * v[k+2];
            a3 += mrow[k+3] * v[k+3];
        }
        float acc = (a0+a1) + (a2+a3);
        __syncthreads();
        v[n] = acc;
        __syncthreads();
    }
    g_Spart[r*NORD + n] = sacc;
}

// ---------------- EW = E @ W, eb = E @ b ----------------
__global__ void ew_kernel(const float* __restrict__ E, const float* __restrict__ W,
                          const float* __restrict__ bm) {
    __shared__ float erow[NORD];
    __shared__ float red[NORD];
    int p = blockIdx.x, m = threadIdx.x;
    float e = E[p*NORD + m];
    erow[m] = e;
    red[m]  = e * bm[m];
    __syncthreads();
    float a0=0.f, a1=0.f, a2=0.f, a3=0.f;
#pragma unroll
    for (int n = 0; n < NORD; n += 4) {
        a0 += erow[n+0] * W[(n+0)*NORD + m];
        a1 += erow[n+1] * W[(n+1)*NORD + m];
        a2 += erow[n+2] * W[(n+2)*NORD + m];
        a3 += erow[n+3] * W[(n+3)*NORD + m];
    }
    g_EW[p*NORD + m] = (a0+a1) + (a2+a3);
    if (m < 32) {
        float vv = red[m] + red[m + 32];
#pragma unroll
        for (int off = 16; off > 0; off >>= 1)
            vv += __shfl_down_sync(0xffffffffu, vv, off);
        if (m == 0) g_eb[p] = vv;
    }
}

// ---------------- S reduce + g = EW @ S ----------------
__global__ void vecs_kernel() {
    __shared__ float S[NORD];
    int tid = threadIdx.x;
    if (tid < NORD) {
        float s = 0.f;
#pragma unroll
        for (int r = 0; r < 16; r++) s += g_Spart[r*NORD + tid];
        S[tid] = s;
    }
    __syncthreads();
    if (tid < PRED) {
        float a0=0.f, a1=0.f;
#pragma unroll
        for (int n = 0; n < NORD; n += 2) {
            a0 += g_EW[tid*NORD + n    ] * S[n    ];
            a1 += g_EW[tid*NORD + n + 1] * S[n + 1];
        }
        g_g[tid] = a0 + a1;
    }
}

// ---------------- GEMM1: XK[m,n] = sum_t x_raw[m,t] * Kt[t,n], fused stats ----------------
// grid (81, 9), block 128. Mtile=64, N=64 (full), t-chunk 80.
__global__ void __launch_bounds__(128) gemm1_kernel(const float* __restrict__ x) {
    __shared__ __align__(16) float Xs[16][64];
    __shared__ __align__(16) float Ks[16][64];
    __shared__ float reds[2][64];
    __shared__ float redq[2][64];

    const int tid   = threadIdx.x;
    const int mbase = blockIdx.x * 64;
    const int h     = blockIdx.y;
    const int t0    = h * TCHUNK;

    const int lm = tid & 63;     // load row (m and n share the pattern)
    const int lw = tid >> 6;     // 0/1
    const int m_load = mbase + lm;
    const int bidx   = m_load / CIN;
    const int chl    = m_load - bidx * CIN;
    const float* xrow = x + (size_t)bidx * ROW_STRIDE + chl;
    const bool mval   = (m_load < M_TOT);

    const int tm = tid & 7;      // 8 groups of 8 m-rows
    const int tn = tid >> 3;     // 16 groups of 4 n-cols

    float acc[8][4];
#pragma unroll
    for (int i = 0; i < 8; i++)
#pragma unroll
        for (int j = 0; j < 4; j++) acc[i][j] = 0.f;
    float psum = 0.f, psq = 0.f;

    for (int kt = 0; kt < TCHUNK/16; kt++) {
        const int tb = t0 + kt*16;
#pragma unroll
        for (int i = 0; i < 8; i++) {
            const int tt = lw + 2*i;
            float xv = mval ? xrow[(tb + tt) * CIN] : 0.f;
            Xs[tt][lm] = xv;
            psum += xv;
            psq  += xv * xv;
            Ks[tt][lm] = g_Kt[(tb + tt) * NORD + lm];
        }
        __syncthreads();
#pragma unroll
        for (int tt = 0; tt < 16; tt++) {
            const float4 a0 = *(const float4*)&Xs[tt][tm*8];
            const float4 a1 = *(const float4*)&Xs[tt][tm*8 + 4];
            const float4 b  = *(const float4*)&Ks[tt][tn*4];
            float av[8] = {a0.x, a0.y, a0.z, a0.w, a1.x, a1.y, a1.z, a1.w};
            float bv[4] = {b.x, b.y, b.z, b.w};
#pragma unroll
            for (int mi = 0; mi < 8; mi++)
#pragma unroll
                for (int ni = 0; ni < 4; ni++)
                    acc[mi][ni] += av[mi] * bv[ni];
        }
        __syncthreads();
    }

    float* xk = g_XK[h];
#pragma unroll
    for (int mi = 0; mi < 8; mi++) {
        const int m = mbase + tm*8 + mi;
        float4 v;
        v.x = acc[mi][0]; v.y = acc[mi][1]; v.z = acc[mi][2]; v.w = acc[mi][3];
        *(float4*)&xk[(size_t)m * NORD + tn*4] = v;
    }
    reds[lw][lm] = psum;
    redq[lw][lm] = psq;
    __syncthreads();
    if (tid < 64) {
        g_rsum[h][mbase + tid] = reds[0][tid] + reds[1][tid];
        g_rsq [h][mbase + tid] = redq[0][tid] + redq[1][tid];
    }
}

// ---------------- reduce t-split partials ----------------
__global__ void xkred_kernel() {
    int i = blockIdx.x * 256 + threadIdx.x;   // i < MPAD*NORD
    float s = 0.f;
#pragma unroll
    for (int h = 0; h < TSPLIT; h++) s += g_XK[h][i];
    g_XKr[i] = s;
}

__global__ void statsf_kernel() {
    int m = blockIdx.x * 256 + threadIdx.x;
    if (m >= M_TOT) return;
    float s = 0.f, q = 0.f;
#pragma unroll
    for (int h = 0; h < TSPLIT; h++) { s += g_rsum[h][m]; q += g_rsq[h][m]; }
    float mean = s * (1.0f / 720.0f);
    float var  = q * (1.0f / 720.0f) - mean * mean;
    float sd   = sqrtf(var + 1e-5f);
    g_mean[m]   = mean;
    g_std[m]    = sd;
    g_invstd[m] = 1.0f / sd;
}

// ---------------- GEMM2 + epilogue: out[b,p,ch] ----------------
// grid (162, 6), block 128. Mtile=32, Ptile=128, K=64.
__global__ void __launch_bounds__(128) gemm2_kernel(float* __restrict__ out,
                                                    const float* __restrict__ aw,
                                                    const float* __restrict__ ab) {
    __shared__ __align__(16) float XKs[16][36];
    __shared__ __align__(16) float EWs[16][132];

    const int tid   = threadIdx.x;
    const int mbase = blockIdx.x * 32;
    const int pbase = blockIdx.y * 128;
    const int tm = tid & 7;      // 8 groups of 4 m
    const int tp = tid >> 3;     // 16 groups of 8 p
    const int lnn = tid & 15;
    const int lrow = tid >> 4;   // 0..7

    float acc[4][8];
#pragma unroll
    for (int i = 0; i < 4; i++)
#pragma unroll
        for (int j = 0; j < 8; j++) acc[i][j] = 0.f;

    for (int kt = 0; kt < 4; kt++) {
        const int nb = kt * 16;
#pragma unroll
        for (int i = 0; i < 4; i++) {
            const int mm = lrow + 8*i;
            XKs[lnn][mm] = g_XKr[(size_t)(mbase + mm) * NORD + nb + lnn];
        }
#pragma unroll
        for (int i = 0; i < 16; i++) {
            const int pp = lrow + 8*i;
            const int p  = pbase + pp;
            EWs[lnn][pp] = (p < PRED) ? g_EW[(size_t)p * NORD + nb + lnn] : 0.f;
        }
        __syncthreads();
#pragma unroll
        for (int nn = 0; nn < 16; nn++) {
            const float4 a  = *(const float4*)&XKs[nn][tm*4];
            const float4 b0 = *(const float4*)&EWs[nn][tp*8];
            const float4 b1 = *(const float4*)&EWs[nn][tp*8 + 4];
            float av[4] = {a.x, a.y, a.z, a.w};
            float bv[8] = {b0.x, b0.y, b0.z, b0.w, b1.x, b1.y, b1.z, b1.w};
#pragma unroll
            for (int mi = 0; mi < 4; mi++)
#pragma unroll
                for (int pi = 0; pi < 8; pi++)
                    acc[mi][pi] += av[mi] * bv[pi];
        }
        __syncthreads();
    }

    // epilogue: pre = alpha*Z + beta*g[p] + eb[p];  out = (pre-ab)/(aw+1e-10)*std + mean
    float gv[8], ebv[8];
#pragma unroll
    for (int pi = 0; pi < 8; pi++) {
        int p = pbase + tp*8 + pi;
        gv[pi]  = (p < PRED) ? g_g[p]  : 0.f;
        ebv[pi] = (p < PRED) ? g_eb[p] : 0.f;
    }
#pragma unroll
    for (int mi = 0; mi < 4; mi++) {
        const int m = mbase + tm*4 + mi;
        if (m >= M_TOT) continue;
        const int bidx = m / CIN;
        const int ch   = m - bidx * CIN;
        const float mean = g_mean[m];
        const float istd = g_invstd[m];
        const float sd   = g_std[m];
        const float awv  = aw[ch];
        const float abv  = ab[ch];
        const float alpha = istd * awv;
        const float beta  = abv - mean * alpha;
        const float inv_aw = 1.0f / (awv + 1e-10f);
        float* obase = out + (size_t)bidx * ROW_STRIDE + ch;
#pragma unroll
        for (int pi = 0; pi < 8; pi++) {
            const int p = pbase + tp*8 + pi;
            if (p < PRED) {
                float pre = alpha * acc[mi][pi] + beta * gv[pi] + ebv[pi];
                obase[(size_t)p * CIN] = (pre - abv) * inv_aw * sd + mean;
            }
        }
    }
}

// ---------------- launcher ----------------
extern "C" void kernel_launch(void* const* d_in, const int* in_sizes, int n_in,
                              void* d_out, int out_size) {
    (void)in_sizes; (void)n_in; (void)out_size;
    const float* x  = (const float*)d_in[0];   // x_enc (16,720,321)
    const float* A  = (const float*)d_in[1];   // A (64,64)
    const float* Bv = (const float*)d_in[2];   // B_vec (64)
    const float* E  = (const float*)d_in[3];   // eval_matrix (720,64)
    const float* W  = (const float*)d_in[4];   // W_mlp (64,64)
    const float* bm = (const float*)d_in[5];   // b_mlp (64)
    const float* aw = (const float*)d_in[6];   // affine_weight (321)
    const float* ab = (const float*)d_in[7];   // affine_bias (321)
    float* out = (float*)d_out;

    // K-matrix pipeline: A^2 -> A^4 -> A^8 -> A^16, seeds A^r B, 16 chains
    pow2_kernel<<<64, 64>>>(A, 0);
    pow2_kernel<<<64, 64>>>(A, 1);
    pow2_kernel<<<64, 64>>>(A, 2);
    pow2_kernel<<<64, 64>>>(A, 3);
    seeds_kernel<<<1, 64>>>(A, Bv);
    chains_kernel<<<16, 64>>>();

    // fold W/b into eval matrix; g = EW @ S
    ew_kernel<<<PRED, 64>>>(E, W, bm);
    vecs_kernel<<<1, 768>>>();

    // main GEMMs
    gemm1_kernel<<<dim3(81, TSPLIT), 128>>>(x);
    xkred_kernel<<<(MPAD * NORD) / 256, 256>>>();
    statsf_kernel<<<(M_TOT + 255) / 256, 256>>>();
    gemm2_kernel<<<dim3(MPAD / 32, 6), 128>>>(out, aw, ab);
}

// round 5
// speedup vs baseline: 1.3199x; 1.3199x over previous
#include <cuda_runtime.h>

// Problem constants
#define BATCH 16
#define SEQ   720
#define CIN   321
#define NORD  64
#define PRED  720
#define M_TOT (BATCH*CIN)        // 5136
#define MPAD  5184               // 81*64
#define TSPLIT 9
#define TCHUNK 80                // 720/9
#define ROW_STRIDE (SEQ*CIN)     // 231120
#define TSTRIDE 68               // padded transpose stride (floats), 16B-aligned rows

typedef unsigned long long ull;

// ---------------- packed f32x2 helpers ----------------
__device__ __forceinline__ ull fma2(ull a, ull b, ull c) {
    ull d;
    asm("fma.rn.f32x2 %0, %1, %2, %3;" : "=l"(d) : "l"(a), "l"(b), "l"(c));
    return d;
}
__device__ __forceinline__ ull dup2(float x) {
    ull d; asm("mov.b64 %0, {%1, %1};" : "=l"(d) : "f"(x)); return d;
}
__device__ __forceinline__ float2 upk2(ull v) {
    float x, y; asm("mov.b64 {%0, %1}, %2;" : "=f"(x), "=f"(y) : "l"(v));
    return make_float2(x, y);
}

// ---------------- device scratch ----------------
__device__ float g_Kt [PRED*NORD];      // Kt[t][n] = (A^(719-t) B)[n]
__device__ float g_Spart[16*NORD];
__device__ float g_EW [PRED*NORD];      // (E @ W)[p][n]
__device__ float g_eb [PRED];           // E @ b_mlp
__device__ float g_XK [TSPLIT][MPAD*NORD];
__device__ float g_XKp[MPAD*NORD];      // alpha-folded operand for GEMM2
__device__ float g_rsum[TSPLIT][MPAD];
__device__ float g_rsq [TSPLIT][MPAD];
__device__ float g_mean[MPAD];
__device__ float g_std [MPAD];

// ============================================================================
// buildk: ONE launch replacing pow2 x4 + seeds + chains + ew.
// Blocks 0..15 : each redundantly squares A -> A^16 (with transposed copies),
//                computes its own seed A^r B, then runs its 45-step chain
//                writing Kt rows (s = 16j + r) and its partial state sum.
// Blocks 16..31: compute EW = E @ W and eb = E @ b (45 p-rows each).
// Dynamic smem: [AT 64x68][T 64x68][N0 64x64][N1 64x64] = 16896 floats.
// ============================================================================
__global__ void __launch_bounds__(256) buildk_kernel(
    const float* __restrict__ A, const float* __restrict__ Bv,
    const float* __restrict__ E, const float* __restrict__ W,
    const float* __restrict__ bm)
{
    extern __shared__ float sh[];
    const int tid = threadIdx.x;
    const int bid = blockIdx.x;

    if (bid >= 16) {
        // ---------------- EW / eb blocks ----------------
        float* Wsh = sh;               // 4096
        float* Esh = sh + 4096;        // 45*64 = 2880
        __shared__ float bsh[NORD];
        const int e = bid - 16;
        for (int i = tid; i < NORD*NORD; i += 256) Wsh[i] = W[i];
        for (int i = tid; i < 45*NORD; i += 256)  Esh[i] = E[e*45*NORD + i];
        if (tid < NORD) bsh[tid] = bm[tid];
        __syncthreads();
        for (int idx = tid; idx < 45*NORD; idx += 256) {
            const int pl = idx >> 6, m = idx & 63;
            float a0 = 0.f, a1 = 0.f;
#pragma unroll
            for (int n = 0; n < NORD; n += 2) {
                a0 += Esh[pl*NORD + n    ] * Wsh[(n    )*NORD + m];
                a1 += Esh[pl*NORD + n + 1] * Wsh[(n + 1)*NORD + m];
            }
            g_EW[(e*45 + pl)*NORD + m] = a0 + a1;
        }
        if (tid < 45) {
            float a = 0.f;
#pragma unroll
            for (int n = 0; n < NORD; n++) a += Esh[tid*NORD + n] * bsh[n];
            g_eb[e*45 + tid] = a;
        }
        return;
    }

    // ---------------- squaring + chain blocks ----------------
    float* AT = sh;                     // 64*68
    float* T  = sh + NORD*TSTRIDE;      // 64*68
    float* N0 = sh + 2*NORD*TSTRIDE;    // 64*64
    float* N1 = N0 + NORD*NORD;         // 64*64
    __shared__ float vsh[NORD];
    __shared__ float pb[256];

    // load A into N0 and its transpose into AT
    for (int i = tid; i < NORD*NORD; i += 256) N0[i] = A[i];
    __syncthreads();
    for (int i = tid; i < NORD*NORD; i += 256) {
        const int r = i >> 6, c = i & 63;
        AT[c*TSTRIDE + r] = N0[i];      // AT[k][n] = A[n][k]
    }
    __syncthreads();

    // 4 squarings: A^2, A^4, A^8, A^16.  dst[i][j] = sum_k srcT[k][i]*srcN[k][j]
    float* srcN = N0;
    float* srcT = AT;
    float* dstN = N1;
    const int ig = tid >> 4;            // 0..15  (i = ig*4)
    const int jg = tid & 15;            // 0..15  (j = jg*4)
#pragma unroll
    for (int s = 0; s < 4; s++) {
        ull acc[4][2];
#pragma unroll
        for (int ii = 0; ii < 4; ii++) { acc[ii][0] = 0ull; acc[ii][1] = 0ull; }
#pragma unroll 8
        for (int k = 0; k < NORD; k++) {
            const float4 a = *(const float4*)&srcT[k*TSTRIDE + ig*4];
            const ulonglong2 b = *(const ulonglong2*)&srcN[k*NORD + jg*4];
            float av[4] = {a.x, a.y, a.z, a.w};
#pragma unroll
            for (int ii = 0; ii < 4; ii++) {
                const ull am = dup2(av[ii]);
                acc[ii][0] = fma2(am, b.x, acc[ii][0]);
                acc[ii][1] = fma2(am, b.y, acc[ii][1]);
            }
        }
#pragma unroll
        for (int ii = 0; ii < 4; ii++) {
            const float2 lo = upk2(acc[ii][0]);
            const float2 hi = upk2(acc[ii][1]);
            float4 v; v.x = lo.x; v.y = lo.y; v.z = hi.x; v.w = hi.y;
            *(float4*)&dstN[(ig*4 + ii)*NORD + jg*4] = v;
        }
        __syncthreads();
        // transpose dstN -> T
        for (int i = tid; i < NORD*NORD; i += 256)
            T[(i & 63)*TSTRIDE + (i >> 6)] = dstN[i];
        __syncthreads();
        // swap src/dst (T always holds transpose of new src)
        float* tmp = srcN; srcN = dstN; dstN = tmp;
        srcT = T;
    }
    // now: srcN = A^16 (row-major), T = (A^16)^T with TSTRIDE, AT intact.

    const int r = bid;
    const int n = tid & 63, q = tid >> 6;

    // seed: v = A^r B  (r serial matvecs using AT)
    if (tid < NORD) vsh[tid] = Bv[tid];
    __syncthreads();
    for (int stp = 0; stp < r; stp++) {
        float p = 0.f;
#pragma unroll
        for (int kk = 0; kk < 16; kk++) {
            const int k = q*16 + kk;
            p += AT[k*TSTRIDE + n] * vsh[k];
        }
        pb[tid] = p;
        __syncthreads();
        if (tid < NORD) vsh[tid] = pb[tid] + pb[tid+64] + pb[tid+128] + pb[tid+192];
        __syncthreads();
    }

    // chain: 45 steps with M = A^16 (via T). u_{16j+r} emitted each step.
    float sacc = 0.f;
    for (int j = 0; j < 45; j++) {
        if (tid < NORD) {
            const int t = 719 - (16*j + r);
            const float u = vsh[tid];
            g_Kt[t*NORD + tid] = u;
            sacc += u;
        }
        float p = 0.f;
#pragma unroll
        for (int kk = 0; kk < 16; kk++) {
            const int k = q*16 + kk;
            p += T[k*TSTRIDE + n] * vsh[k];
        }
        pb[tid] = p;
        __syncthreads();
        if (tid < NORD) vsh[tid] = pb[tid] + pb[tid+64] + pb[tid+128] + pb[tid+192];
        __syncthreads();
    }
    if (tid < NORD) g_Spart[r*NORD + tid] = sacc;
}

// ============================================================================
// GEMM1: XK[m,n] = sum_t x_raw[m,t] * Kt[t,n], fused mean/var partials.
// grid (81, 9), block 128. Mtile=64, N=64, t-chunk 80. FFMA2 inner loop.
// ============================================================================
__global__ void __launch_bounds__(128) gemm1_kernel(const float* __restrict__ x) {
    __shared__ __align__(16) float Xs[16][64];
    __shared__ __align__(16) float Ks[16][64];
    __shared__ float reds[2][64];
    __shared__ float redq[2][64];

    const int tid   = threadIdx.x;
    const int mbase = blockIdx.x * 64;
    const int h     = blockIdx.y;
    const int t0    = h * TCHUNK;

    const int lm = tid & 63;
    const int lw = tid >> 6;
    const int m_load = mbase + lm;
    const int bidx   = m_load / CIN;
    const int chl    = m_load - bidx * CIN;
    const float* xrow = x + (size_t)bidx * ROW_STRIDE + chl;
    const bool mval   = (m_load < M_TOT);

    const int tm = tid & 7;      // 8 groups of 8 m-rows
    const int tn = tid >> 3;     // 16 groups of 4 n-cols

    ull accp[8][2];
#pragma unroll
    for (int i = 0; i < 8; i++) { accp[i][0] = 0ull; accp[i][1] = 0ull; }
    float psum = 0.f, psq = 0.f;

    for (int kt = 0; kt < TCHUNK/16; kt++) {
        const int tb = t0 + kt*16;
#pragma unroll
        for (int i = 0; i < 8; i++) {
            const int tt = lw + 2*i;
            float xv = mval ? xrow[(tb + tt) * CIN] : 0.f;
            Xs[tt][lm] = xv;
            psum += xv;
            psq  += xv * xv;
            Ks[tt][lm] = g_Kt[(tb + tt) * NORD + lm];
        }
        __syncthreads();
#pragma unroll
        for (int tt = 0; tt < 16; tt++) {
            const float4 a0 = *(const float4*)&Xs[tt][tm*8];
            const float4 a1 = *(const float4*)&Xs[tt][tm*8 + 4];
            const ulonglong2 b = *(const ulonglong2*)&Ks[tt][tn*4];
            float av[8] = {a0.x, a0.y, a0.z, a0.w, a1.x, a1.y, a1.z, a1.w};
#pragma unroll
            for (int mi = 0; mi < 8; mi++) {
                const ull am = dup2(av[mi]);
                accp[mi][0] = fma2(am, b.x, accp[mi][0]);
                accp[mi][1] = fma2(am, b.y, accp[mi][1]);
            }
        }
        __syncthreads();
    }

    float* xk = g_XK[h];
#pragma unroll
    for (int mi = 0; mi < 8; mi++) {
        const int m = mbase + tm*8 + mi;
        const float2 lo = upk2(accp[mi][0]);
        const float2 hi = upk2(accp[mi][1]);
        float4 v; v.x = lo.x; v.y = lo.y; v.z = hi.x; v.w = hi.y;
        *(float4*)&xk[(size_t)m * NORD + tn*4] = v;
    }
    reds[lw][lm] = psum;
    redq[lw][lm] = psq;
    __syncthreads();
    if (tid < 64) {
        g_rsum[h][mbase + tid] = reds[0][tid] + reds[1][tid];
        g_rsq [h][mbase + tid] = redq[0][tid] + redq[1][tid];
    }
}

// ============================================================================
// fuse: reduce t-split partials + stats + S + alpha/beta fold.
// XKp[m,n] = alpha_m * sum_h XK[h][m,n] + beta_m * S[n]
// where alpha = aw[ch]/sd, beta = ab[ch] - mean*alpha.
// grid 81, block 256 (64 m per block).
// ============================================================================
__global__ void __launch_bounds__(256) fuse_kernel(const float* __restrict__ aw,
                                                   const float* __restrict__ ab) {
    __shared__ float alpha_s[64], beta_s[64], Ssh[64];
    const int tid = threadIdx.x;
    const int mb  = blockIdx.x * 64;

    if (tid < 64) {
        const int m = mb + tid;
        float s = 0.f, qq = 0.f;
#pragma unroll
        for (int h = 0; h < TSPLIT; h++) { s += g_rsum[h][m]; qq += g_rsq[h][m]; }
        const float mean = s * (1.0f / 720.0f);
        const float var  = qq * (1.0f / 720.0f) - mean * mean;
        const float sd   = sqrtf(var + 1e-5f);
        const int bidx = m / CIN;
        const int ch   = m - bidx * CIN;   // always < CIN (padding maps into batch 16 range)
        const float awv = aw[ch];
        const float abv = ab[ch];
        const float al  = awv / sd;
        alpha_s[tid] = al;
        beta_s[tid]  = abv - mean * al;
        g_mean[m] = mean;
        g_std[m]  = sd;
    } else if (tid < 128) {
        const int nn = tid - 64;
        float s = 0.f;
#pragma unroll
        for (int rr = 0; rr < 16; rr++) s += g_Spart[rr*NORD + nn];
        Ssh[nn] = s;
    }
    __syncthreads();

#pragma unroll
    for (int i = 0; i < 16; i++) {
        const int idx  = i*256 + tid;          // 0..4095
        const int base = mb*NORD + idx;
        float v = 0.f;
#pragma unroll
        for (int h = 0; h < TSPLIT; h++) v += g_XK[h][base];
        const int ml = idx >> 6, nn = idx & 63;
        g_XKp[base] = alpha_s[ml]*v + beta_s[ml]*Ssh[nn];
    }
}

// ============================================================================
// GEMM2 + epilogue: pre[m,p] = sum_n XKp[m,n] EW[p,n] + eb[p];
// out[b,p,ch] = (pre - ab)/(aw+1e-10) * sd + mean.
// grid (162, 6), block 128. Mtile=32, Ptile=128, K=64. FFMA2 inner loop.
// ============================================================================
__global__ void __launch_bounds__(128) gemm2_kernel(float* __restrict__ out,
                                                    const float* __restrict__ aw,
                                                    const float* __restrict__ ab) {
    __shared__ __align__(16) float XKs[16][36];
    __shared__ __align__(16) float EWs[16][132];

    const int tid   = threadIdx.x;
    const int mbase = blockIdx.x * 32;
    const int pbase = blockIdx.y * 128;
    const int tm = tid & 7;      // 8 groups of 4 m
    const int tp = tid >> 3;     // 16 groups of 8 p
    const int lnn = tid & 15;
    const int lrow = tid >> 4;   // 0..7

    ull accp[4][4];
#pragma unroll
    for (int i = 0; i < 4; i++)
#pragma unroll
        for (int j = 0; j < 4; j++) accp[i][j] = 0ull;

    for (int kt = 0; kt < 4; kt++) {
        const int nb = kt * 16;
#pragma unroll
        for (int i = 0; i < 4; i++) {
            const int mm = lrow + 8*i;
            XKs[lnn][mm] = g_XKp[(size_t)(mbase + mm) * NORD + nb + lnn];
        }
#pragma unroll
        for (int i = 0; i < 16; i++) {
            const int pp = lrow + 8*i;
            const int p  = pbase + pp;
            EWs[lnn][pp] = (p < PRED) ? g_EW[(size_t)p * NORD + nb + lnn] : 0.f;
        }
        __syncthreads();
#pragma unroll
        for (int nn = 0; nn < 16; nn++) {
            const float4 a = *(const float4*)&XKs[nn][tm*4];
            const ulonglong2 b0 = *(const ulonglong2*)&EWs[nn][tp*8];
            const ulonglong2 b1 = *(const ulonglong2*)&EWs[nn][tp*8 + 4];
            float av[4] = {a.x, a.y, a.z, a.w};
#pragma unroll
            for (int mi = 0; mi < 4; mi++) {
                const ull am = dup2(av[mi]);
                accp[mi][0] = fma2(am, b0.x, accp[mi][0]);
                accp[mi][1] = fma2(am, b0.y, accp[mi][1]);
                accp[mi][2] = fma2(am, b1.x, accp[mi][2]);
                accp[mi][3] = fma2(am, b1.y, accp[mi][3]);
            }
        }
        __syncthreads();
    }

    // epilogue
    float ebv[8];
#pragma unroll
    for (int pi = 0; pi < 8; pi++) {
        const int p = pbase + tp*8 + pi;
        ebv[pi] = (p < PRED) ? g_eb[p] : 0.f;
    }
#pragma unroll
    for (int mi = 0; mi < 4; mi++) {
        const int m = mbase + tm*4 + mi;
        if (m >= M_TOT) continue;
        const int bidx = m / CIN;
        const int ch   = m - bidx * CIN;
        const float mean = g_mean[m];
        const float sd   = g_std[m];
        const float abv  = ab[ch];
        const float scale = sd / (aw[ch] + 1e-10f);
        float accf[8];
        {
            const float2 p0 = upk2(accp[mi][0]);
            const float2 p1 = upk2(accp[mi][1]);
            const float2 p2 = upk2(accp[mi][2]);
            const float2 p3 = upk2(accp[mi][3]);
            accf[0]=p0.x; accf[1]=p0.y; accf[2]=p1.x; accf[3]=p1.y;
            accf[4]=p2.x; accf[5]=p2.y; accf[6]=p3.x; accf[7]=p3.y;
        }
        float* obase = out + (size_t)bidx * ROW_STRIDE + ch;
#pragma unroll
        for (int pi = 0; pi < 8; pi++) {
            const int p = pbase + tp*8 + pi;
            if (p < PRED) {
                const float pre = accf[pi] + ebv[pi];
                obase[(size_t)p * CIN] = (pre - abv) * scale + mean;
            }
        }
    }
}

// ---------------- launcher: 4 graph nodes ----------------
extern "C" void kernel_launch(void* const* d_in, const int* in_sizes, int n_in,
                              void* d_out, int out_size) {
    (void)in_sizes; (void)n_in; (void)out_size;
    const float* x  = (const float*)d_in[0];   // x_enc (16,720,321)
    const float* A  = (const float*)d_in[1];   // A (64,64)
    const float* Bv = (const float*)d_in[2];   // B_vec (64)
    const float* E  = (const float*)d_in[3];   // eval_matrix (720,64)
    const float* W  = (const float*)d_in[4];   // W_mlp (64,64)
    const float* bm = (const float*)d_in[5];   // b_mlp (64)
    const float* aw = (const float*)d_in[6];   // affine_weight (321)
    const float* ab = (const float*)d_in[7];   // affine_bias (321)
    float* out = (float*)d_out;

    const int buildk_smem = (2*NORD*TSTRIDE + 2*NORD*NORD) * (int)sizeof(float); // 67584
    cudaFuncSetAttribute(buildk_kernel, cudaFuncAttributeMaxDynamicSharedMemorySize, buildk_smem);

    buildk_kernel<<<32, 256, buildk_smem>>>(A, Bv, E, W, bm);
    gemm1_kernel<<<dim3(81, TSPLIT), 128>>>(x);
    fuse_kernel<<<81, 256>>>(aw, ab);
    gemm2_kernel<<<dim3(MPAD/32, 6), 128>>>(out, aw, ab);
}

// round 6
// speedup vs baseline: 1.4763x; 1.1185x over previous
#include <cuda_runtime.h>

// Problem constants
#define BATCH 16
#define SEQ   720
#define CIN   321
#define NORD  64
#define PRED  720
#define M_TOT (BATCH*CIN)        // 5136
#define MPAD  5248               // 41 * 128
#define TSPLIT 6
#define TCHUNK 120               // 720/6
#define KCH   24                 // k-chunk in gemm1 (5 per TCHUNK)
#define ROW_STRIDE (SEQ*CIN)     // 231120
#define TSTRIDE 68               // padded transpose stride (floats)
#define NCHAIN 32                // chains in buildk (A^32 stride)

typedef unsigned long long ull;

// ---------------- packed f32x2 helpers ----------------
__device__ __forceinline__ ull fma2(ull a, ull b, ull c) {
    ull d;
    asm("fma.rn.f32x2 %0, %1, %2, %3;" : "=l"(d) : "l"(a), "l"(b), "l"(c));
    return d;
}
__device__ __forceinline__ ull dup2(float x) {
    ull d; asm("mov.b64 %0, {%1, %1};" : "=l"(d) : "f"(x)); return d;
}
__device__ __forceinline__ float2 upk2(ull v) {
    float x, y; asm("mov.b64 {%0, %1}, %2;" : "=f"(x), "=f"(y) : "l"(v));
    return make_float2(x, y);
}

// ---------------- device scratch ----------------
__device__ float g_Kt   [PRED*NORD];        // Kt[t][n] = (A^(719-t) B)[n]
__device__ float g_Spart[NCHAIN*NORD];
__device__ float g_EWT  [NORD*PRED];        // (E @ W) transposed: [n][p]
__device__ float g_eb   [PRED];             // E @ b_mlp
__device__ float g_XK   [TSPLIT][MPAD*NORD];
__device__ float g_XKpT [NORD*MPAD];        // alpha-folded GEMM2 operand, [n][m]
__device__ float g_rsum [TSPLIT][MPAD];
__device__ float g_rsq  [TSPLIT][MPAD];
__device__ float g_mean [MPAD];
__device__ float g_std  [MPAD];

// ============================================================================
// buildk: blocks 0..31 each redundantly square A -> A^2..A^32 (+transposes),
// build their seed A^r B via binary decomposition (<=5 matvecs), then run a
// 23-step chain with A^32 writing Kt rows s = 32j + r.
// Blocks 32..47 compute EWT = (E @ W)^T and eb = E @ b.
// Dynamic smem: 6 transposed powers (64x68) + two 64x64 row-major = 137216 B.
// ============================================================================
__global__ void __launch_bounds__(256) buildk_kernel(
    const float* __restrict__ A, const float* __restrict__ Bv,
    const float* __restrict__ E, const float* __restrict__ W,
    const float* __restrict__ bm)
{
    extern __shared__ float sh[];
    const int tid = threadIdx.x;
    const int bid = blockIdx.x;

    if (bid >= NCHAIN) {
        // ---------------- EWT / eb blocks ----------------
        float* Wsh = sh;               // 4096
        float* Esh = sh + 4096;        // 45*64
        __shared__ float bsh[NORD];
        const int e = bid - NCHAIN;
        for (int i = tid; i < NORD*NORD; i += 256) Wsh[i] = W[i];
        for (int i = tid; i < 45*NORD; i += 256)  Esh[i] = E[e*45*NORD + i];
        if (tid < NORD) bsh[tid] = bm[tid];
        __syncthreads();
        for (int idx = tid; idx < 45*NORD; idx += 256) {
            const int pl = idx >> 6, m = idx & 63;
            float a0 = 0.f, a1 = 0.f;
#pragma unroll
            for (int n = 0; n < NORD; n += 2) {
                a0 += Esh[pl*NORD + n    ] * Wsh[(n    )*NORD + m];
                a1 += Esh[pl*NORD + n + 1] * Wsh[(n + 1)*NORD + m];
            }
            g_EWT[(size_t)m*PRED + e*45 + pl] = a0 + a1;
        }
        if (tid < 45) {
            float a = 0.f;
#pragma unroll
            for (int n = 0; n < NORD; n++) a += Esh[tid*NORD + n] * bsh[n];
            g_eb[e*45 + tid] = a;
        }
        return;
    }

    // ---------------- chain blocks ----------------
    float* TP[6];
#pragma unroll
    for (int i = 0; i < 6; i++) TP[i] = sh + i * NORD * TSTRIDE;
    float* N0 = sh + 6 * NORD * TSTRIDE;
    float* N1 = N0 + NORD*NORD;
    __shared__ float vsh[NORD];
    __shared__ float pb[256];

    for (int i = tid; i < NORD*NORD; i += 256) N0[i] = A[i];
    __syncthreads();
    for (int i = tid; i < NORD*NORD; i += 256)
        TP[0][(i & 63)*TSTRIDE + (i >> 6)] = N0[i];
    __syncthreads();

    // 5 squarings: A^2 .. A^32
    float* srcN = N0;
    float* dstN = N1;
    const int ig = tid >> 4;
    const int jg = tid & 15;
#pragma unroll
    for (int s = 0; s < 5; s++) {
        const float* srcT = TP[s];
        ull acc2[4][2];
#pragma unroll
        for (int ii = 0; ii < 4; ii++) { acc2[ii][0] = 0ull; acc2[ii][1] = 0ull; }
#pragma unroll 8
        for (int k = 0; k < NORD; k++) {
            const float4 a = *(const float4*)&srcT[k*TSTRIDE + ig*4];
            const ulonglong2 b = *(const ulonglong2*)&srcN[k*NORD + jg*4];
            float av[4] = {a.x, a.y, a.z, a.w};
#pragma unroll
            for (int ii = 0; ii < 4; ii++) {
                const ull am = dup2(av[ii]);
                acc2[ii][0] = fma2(am, b.x, acc2[ii][0]);
                acc2[ii][1] = fma2(am, b.y, acc2[ii][1]);
            }
        }
#pragma unroll
        for (int ii = 0; ii < 4; ii++) {
            const float2 lo = upk2(acc2[ii][0]);
            const float2 hi = upk2(acc2[ii][1]);
            float4 v; v.x = lo.x; v.y = lo.y; v.z = hi.x; v.w = hi.y;
            *(float4*)&dstN[(ig*4 + ii)*NORD + jg*4] = v;
        }
        __syncthreads();
        for (int i = tid; i < NORD*NORD; i += 256)
            TP[s+1][(i & 63)*TSTRIDE + (i >> 6)] = dstN[i];
        __syncthreads();
        float* tmp = srcN; srcN = dstN; dstN = tmp;
    }

    const int r = bid;
    const int n = tid & 63, q = tid >> 6;

    // seed: v = A^r B via binary decomposition of r (bits 0..4)
    if (tid < NORD) vsh[tid] = Bv[tid];
    __syncthreads();
#pragma unroll
    for (int b = 0; b < 5; b++) {
        if ((r >> b) & 1) {
            float p = 0.f;
#pragma unroll
            for (int kk = 0; kk < 16; kk++) {
                const int k = q*16 + kk;
                p += TP[b][k*TSTRIDE + n] * vsh[k];
            }
            pb[tid] = p;
            __syncthreads();
            if (tid < NORD) vsh[tid] = pb[tid] + pb[tid+64] + pb[tid+128] + pb[tid+192];
            __syncthreads();
        }
    }

    // chain: steps with M = A^32; emit s = 32j + r (< 720)
    const float* T32 = TP[5];
    float sacc = 0.f;
    for (int j = 0; j < 23; j++) {
        const int s_exp = 32*j + r;
        if (s_exp < 720 && tid < NORD) {
            const float u = vsh[tid];
            g_Kt[(719 - s_exp)*NORD + tid] = u;
            sacc += u;
        }
        if (j < 22) {
            float p = 0.f;
#pragma unroll
            for (int kk = 0; kk < 16; kk++) {
                const int k = q*16 + kk;
                p += T32[k*TSTRIDE + n] * vsh[k];
            }
            pb[tid] = p;
            __syncthreads();
            if (tid < NORD) vsh[tid] = pb[tid] + pb[tid+64] + pb[tid+128] + pb[tid+192];
            __syncthreads();
        }
    }
    if (tid < NORD) g_Spart[r*NORD + tid] = sacc;
}

// ============================================================================
// GEMM1: XK[m,n] = sum_t x_raw[m,t] * Kt[t,n], fused mean/var partials.
// grid (41, 6), block 128. Mtile=128, N=64, 8m x 8n per thread, FFMA2.
// ============================================================================
__global__ void __launch_bounds__(128) gemm1_kernel(const float* __restrict__ x) {
    __shared__ __align__(16) float Xs[KCH][128];
    __shared__ __align__(16) float Ks[KCH][64];

    const int tid   = threadIdx.x;
    const int mbase = blockIdx.x * 128;
    const int h     = blockIdx.y;
    const int t0    = h * TCHUNK;

    const int m_load = mbase + tid;
    const int bidx   = m_load / CIN;
    const int chl    = m_load - bidx * CIN;
    const float* xrow = x + (size_t)bidx * ROW_STRIDE + chl;
    const bool mval   = (m_load < M_TOT);

    const int tn = tid & 7;      // n = tn*8 + ni
    const int tm = tid >> 3;     // m = mbase + tm*8 + mi

    ull acc[8][4];
#pragma unroll
    for (int i = 0; i < 8; i++)
#pragma unroll
        for (int j = 0; j < 4; j++) acc[i][j] = 0ull;
    float psum = 0.f, psq = 0.f;

    for (int kt = 0; kt < TCHUNK/KCH; kt++) {
        const int tb = t0 + kt*KCH;
#pragma unroll
        for (int tt = 0; tt < KCH; tt++) {
            float xv = mval ? xrow[(tb + tt) * CIN] : 0.f;
            Xs[tt][tid] = xv;
            psum += xv;
            psq  += xv * xv;
        }
#pragma unroll
        for (int i = 0; i < (KCH*64)/128; i++) {
            const int idx = tid + i*128;
            const int tt = idx >> 6, nn = idx & 63;
            Ks[tt][nn] = g_Kt[(tb + tt) * NORD + nn];
        }
        __syncthreads();
#pragma unroll 8
        for (int tt = 0; tt < KCH; tt++) {
            const float4 a0 = *(const float4*)&Xs[tt][tm*8];
            const float4 a1 = *(const float4*)&Xs[tt][tm*8 + 4];
            const ulonglong2 b0 = *(const ulonglong2*)&Ks[tt][tn*8];
            const ulonglong2 b1 = *(const ulonglong2*)&Ks[tt][tn*8 + 4];
            float av[8] = {a0.x, a0.y, a0.z, a0.w, a1.x, a1.y, a1.z, a1.w};
#pragma unroll
            for (int mi = 0; mi < 8; mi++) {
                const ull am = dup2(av[mi]);
                acc[mi][0] = fma2(am, b0.x, acc[mi][0]);
                acc[mi][1] = fma2(am, b0.y, acc[mi][1]);
                acc[mi][2] = fma2(am, b1.x, acc[mi][2]);
                acc[mi][3] = fma2(am, b1.y, acc[mi][3]);
            }
        }
        __syncthreads();
    }

    float* xk = g_XK[h];
#pragma unroll
    for (int mi = 0; mi < 8; mi++) {
        const int m = mbase + tm*8 + mi;
        const float2 p0 = upk2(acc[mi][0]);
        const float2 p1 = upk2(acc[mi][1]);
        const float2 p2 = upk2(acc[mi][2]);
        const float2 p3 = upk2(acc[mi][3]);
        float4 v0; v0.x = p0.x; v0.y = p0.y; v0.z = p1.x; v0.w = p1.y;
        float4 v1; v1.x = p2.x; v1.y = p2.y; v1.z = p3.x; v1.w = p3.y;
        *(float4*)&xk[(size_t)m * NORD + tn*8    ] = v0;
        *(float4*)&xk[(size_t)m * NORD + tn*8 + 4] = v1;
    }
    g_rsum[h][m_load] = psum;
    g_rsq [h][m_load] = psq;
}

// ============================================================================
// fuse: reduce t-split partials + stats + S + alpha/beta fold + transpose.
// XKpT[n, m] = alpha_m * sum_h XK[h][m,n] + beta_m * S[n]
// grid 82, block 256 (64 m per block).
// ============================================================================
__global__ void __launch_bounds__(256) fuse_kernel(const float* __restrict__ aw,
                                                   const float* __restrict__ ab) {
    __shared__ float TT[64*65];
    __shared__ float alpha_s[64], beta_s[64], Ssh[64];
    const int tid = threadIdx.x;
    const int mb  = blockIdx.x * 64;

    if (tid < 64) {
        const int m = mb + tid;
        float s = 0.f, qq = 0.f;
#pragma unroll
        for (int h = 0; h < TSPLIT; h++) { s += g_rsum[h][m]; qq += g_rsq[h][m]; }
        const float mean = s * (1.0f / 720.0f);
        const float var  = qq * (1.0f / 720.0f) - mean * mean;
        const float sd   = sqrtf(var + 1e-5f);
        const int bidx = m / CIN;
        const int ch   = m - bidx * CIN;
        const float al = aw[ch] / sd;
        alpha_s[tid] = al;
        beta_s[tid]  = ab[ch] - mean * al;
        g_mean[m] = mean;
        g_std[m]  = sd;
    } else if (tid < 128) {
        const int nn = tid - 64;
        float s = 0.f;
#pragma unroll
        for (int rr = 0; rr < NCHAIN; rr++) s += g_Spart[rr*NORD + nn];
        Ssh[nn] = s;
    }
    __syncthreads();

#pragma unroll
    for (int i = 0; i < 16; i++) {
        const int idx = i*256 + tid;           // 0..4095
        const int ml = idx >> 6, nn = idx & 63;
        float v = 0.f;
#pragma unroll
        for (int h = 0; h < TSPLIT; h++) v += g_XK[h][(size_t)(mb + ml)*NORD + nn];
        TT[nn*65 + ml] = alpha_s[ml]*v + beta_s[ml]*Ssh[nn];
    }
    __syncthreads();
#pragma unroll
    for (int i = 0; i < 16; i++) {
        const int idx = i*256 + tid;
        const int nn = idx >> 6, ml = idx & 63;
        g_XKpT[(size_t)nn*MPAD + mb + ml] = TT[nn*65 + ml];
    }
}

// ============================================================================
// GEMM2 + epilogue: pre[m,p] = sum_n XKpT[n,m] EWT[n,p] + eb[p];
// out[b,p,ch] = (pre - ab)/(aw+1e-10) * sd + mean. Coalesced stores via smem.
// grid (82, 6), block 128. Mtile=64, Ptile=128, K=64 resident. 8m x 8p / thread.
// ============================================================================
__global__ void __launch_bounds__(128) gemm2_kernel(float* __restrict__ out,
                                                    const float* __restrict__ aw,
                                                    const float* __restrict__ ab) {
    __shared__ __align__(16) float pool[12288];   // 48 KB
    float* Xs = pool;          // [64][64]
    float* Es = pool + 4096;   // [64][128]

    const int tid   = threadIdx.x;
    const int mbase = blockIdx.x * 64;
    const int pbase = blockIdx.y * 128;
    const int tm = tid & 7;      // m = mbase + tm*8 + mi
    const int tp = tid >> 3;     // p = pbase + tp*8 + pi

    // stage Xs (XKpT tile): coalesced, conflict-free
#pragma unroll
    for (int i = 0; i < 8; i++) {
        const int idx = tid + i*128;            // 0..1023
        const int n = idx >> 4, mg = idx & 15;
        *(float4*)&Xs[n*64 + mg*4] =
            *(const float4*)&g_XKpT[(size_t)n*MPAD + mbase + mg*4];
    }
    // stage Es (EWT tile) with p guard
#pragma unroll
    for (int i = 0; i < 16; i++) {
        const int idx = tid + i*128;            // 0..2047
        const int n = idx >> 5, pg = idx & 31;
        const int p = pbase + pg*4;
        float4 v = make_float4(0.f, 0.f, 0.f, 0.f);
        if (p < PRED) v = *(const float4*)&g_EWT[(size_t)n*PRED + p];
        *(float4*)&Es[n*128 + pg*4] = v;
    }
    __syncthreads();

    ull acc[8][4];
#pragma unroll
    for (int i = 0; i < 8; i++)
#pragma unroll
        for (int j = 0; j < 4; j++) acc[i][j] = 0ull;

#pragma unroll 8
    for (int k = 0; k < 64; k++) {
        const float4 a0 = *(const float4*)&Xs[k*64 + tm*8];
        const float4 a1 = *(const float4*)&Xs[k*64 + tm*8 + 4];
        const ulonglong2 b0 = *(const ulonglong2*)&Es[k*128 + tp*8];
        const ulonglong2 b1 = *(const ulonglong2*)&Es[k*128 + tp*8 + 4];
        float av[8] = {a0.x, a0.y, a0.z, a0.w, a1.x, a1.y, a1.z, a1.w};
#pragma unroll
        for (int mi = 0; mi < 8; mi++) {
            const ull am = dup2(av[mi]);
            acc[mi][0] = fma2(am, b0.x, acc[mi][0]);
            acc[mi][1] = fma2(am, b0.y, acc[mi][1]);
            acc[mi][2] = fma2(am, b1.x, acc[mi][2]);
            acc[mi][3] = fma2(am, b1.y, acc[mi][3]);
        }
    }
    __syncthreads();   // done reading Xs/Es; pool will be reused as Os

    // epilogue values staged into Os[p_loc][m_loc] (stride 68)
    float* Os = pool;
    float ebv[8];
#pragma unroll
    for (int pi = 0; pi < 8; pi++) {
        const int p = pbase + tp*8 + pi;
        ebv[pi] = (p < PRED) ? g_eb[p] : 0.f;
    }
#pragma unroll
    for (int mi = 0; mi < 8; mi++) {
        const int m = mbase + tm*8 + mi;
        const float mean = g_mean[m];
        const float sd   = g_std[m];
        const int bi = m / CIN;
        const int ch = m - bi * CIN;
        const float abv = ab[ch];
        const float scale = sd / (aw[ch] + 1e-10f);
        float accf[8];
        {
            const float2 p0 = upk2(acc[mi][0]);
            const float2 p1 = upk2(acc[mi][1]);
            const float2 p2 = upk2(acc[mi][2]);
            const float2 p3 = upk2(acc[mi][3]);
            accf[0]=p0.x; accf[1]=p0.y; accf[2]=p1.x; accf[3]=p1.y;
            accf[4]=p2.x; accf[5]=p2.y; accf[6]=p3.x; accf[7]=p3.y;
        }
#pragma unroll
        for (int pi = 0; pi < 8; pi++) {
            const float val = (accf[pi] + ebv[pi] - abv) * scale + mean;
            Os[(tp*8 + pi)*68 + tm*8 + mi] = val;
        }
    }
    __syncthreads();

    // coalesced global store: lanes sweep m, loop sweeps p
    const int ml = tid & 63;
    const int ph = tid >> 6;            // 0 or 1
    const int m  = mbase + ml;
    if (m < M_TOT) {
        const int bi = m / CIN;
        const int ch = m - bi * CIN;
        float* ob = out + (size_t)bi * ROW_STRIDE + ch;
        const int plim = (PRED - pbase < 128) ? (PRED - pbase) : 128;
        for (int pl = ph; pl < plim; pl += 2)
            ob[(size_t)(pbase + pl) * CIN] = Os[pl*68 + ml];
    }
}

// ---------------- launcher: 4 graph nodes ----------------
extern "C" void kernel_launch(void* const* d_in, const int* in_sizes, int n_in,
                              void* d_out, int out_size) {
    (void)in_sizes; (void)n_in; (void)out_size;
    const float* x  = (const float*)d_in[0];   // x_enc (16,720,321)
    const float* A  = (const float*)d_in[1];   // A (64,64)
    const float* Bv = (const float*)d_in[2];   // B_vec (64)
    const float* E  = (const float*)d_in[3];   // eval_matrix (720,64)
    const float* W  = (const float*)d_in[4];   // W_mlp (64,64)
    const float* bm = (const float*)d_in[5];   // b_mlp (64)
    const float* aw = (const float*)d_in[6];   // affine_weight (321)
    const float* ab = (const float*)d_in[7];   // affine_bias (321)
    float* out = (float*)d_out;

    const int buildk_smem = (6*NORD*TSTRIDE + 2*NORD*NORD) * (int)sizeof(float); // 137216
    cudaFuncSetAttribute(buildk_kernel, cudaFuncAttributeMaxDynamicSharedMemorySize, buildk_smem);

    buildk_kernel<<<NCHAIN + 16, 256, buildk_smem>>>(A, Bv, E, W, bm);
    gemm1_kernel<<<dim3(MPAD/128, TSPLIT), 128>>>(x);
    fuse_kernel<<<MPAD/64, 256>>>(aw, ab);
    gemm2_kernel<<<dim3(MPAD/64, 6), 128>>>(out, aw, ab);
}